// round 1
// baseline (speedup 1.0000x reference)
#include <cuda_runtime.h>

#define B_ 4
#define T_ 2048
#define C_ 1024
#define H_ 16
#define D_ 64
#define M_ (B_*T_)

// Scratch (device globals; allocation-free per harness rules)
__device__ float g_q [B_*H_*T_*D_];   // [B,H,T,d]
__device__ float g_k [B_*H_*T_*D_];
__device__ float g_v [B_*H_*T_*D_];
__device__ float g_ao[M_*C_];         // attention output, [B*T, C]

// ---------------------------------------------------------------------------
// Kernel 1: QKV GEMM.  qkv[m, n] = x[m, :] @ w_qkv[:, n] + b_qkv[n]
// 64x64 tile, 16-wide K slices, 4x4 register micro-tile per thread.
// Epilogue scatters into g_q/g_k/g_v in [B,H,T,d] layout (each 64-wide,
// 64-aligned N tile lies inside exactly one head & one of q/k/v).
// ---------------------------------------------------------------------------
__global__ __launch_bounds__(256) void qkv_gemm_kernel(
    const float* __restrict__ x, const float* __restrict__ w,
    const float* __restrict__ bias)
{
    __shared__ float As[16*68];   // [k][m], padded
    __shared__ float Bs[16*68];   // [k][n], padded

    const int tid = threadIdx.x;
    const int n0 = blockIdx.x * 64;
    const int m0 = blockIdx.y * 64;
    const int tx = tid & 15, ty = tid >> 4;
    const int a_m = tid >> 2,  a_k = (tid & 3) << 2;
    const int b_k = tid >> 4,  b_n = (tid & 15) << 2;

    const float* aptr = x + (size_t)(m0 + a_m) * C_ + a_k;
    const float* bptr = w + (size_t)b_k * (3*C_) + n0 + b_n;

    float4 av = *(const float4*)aptr;
    float4 bv = *(const float4*)bptr;

    float acc[4][4];
#pragma unroll
    for (int i = 0; i < 4; i++)
#pragma unroll
        for (int j = 0; j < 4; j++) acc[i][j] = 0.f;

    for (int k0 = 0; k0 < C_; k0 += 16) {
        As[(a_k+0)*68 + a_m] = av.x;
        As[(a_k+1)*68 + a_m] = av.y;
        As[(a_k+2)*68 + a_m] = av.z;
        As[(a_k+3)*68 + a_m] = av.w;
        *(float4*)&Bs[b_k*68 + b_n] = bv;
        __syncthreads();
        if (k0 + 16 < C_) {                       // software prefetch
            av = *(const float4*)(aptr + k0 + 16);
            bv = *(const float4*)(bptr + (size_t)(k0 + 16)*(3*C_));
        }
#pragma unroll
        for (int kk = 0; kk < 16; kk++) {
            float a4[4], b4[4];
            *(float4*)a4 = *(const float4*)&As[kk*68 + (ty<<2)];
            *(float4*)b4 = *(const float4*)&Bs[kk*68 + (tx<<2)];
#pragma unroll
            for (int i = 0; i < 4; i++)
#pragma unroll
                for (int j = 0; j < 4; j++) acc[i][j] += a4[i]*b4[j];
        }
        __syncthreads();
    }

    const int nb   = n0 + (tx<<2);
    const int sect = nb >> 10;          // 0=q 1=k 2=v
    const int cc   = nb & 1023;
    const int h    = cc >> 6;
    const int dd   = cc & 63;
    float* dst = (sect == 0) ? g_q : (sect == 1) ? g_k : g_v;
    float bj[4];
#pragma unroll
    for (int j = 0; j < 4; j++) bj[j] = bias[nb + j];
#pragma unroll
    for (int i = 0; i < 4; i++) {
        int m  = m0 + (ty<<2) + i;
        int bb = m >> 11;               // / T_
        int t  = m & (T_-1);
        float4 o;
        o.x = acc[i][0] + bj[0]; o.y = acc[i][1] + bj[1];
        o.z = acc[i][2] + bj[2]; o.w = acc[i][3] + bj[3];
        *(float4*)(dst + (((size_t)bb*H_ + h)*T_ + t)*D_ + dd) = o;
    }
}

// ---------------------------------------------------------------------------
// Kernel 2: causal flash attention, fp32.  One block = (b,h, 64-row Q tile).
// smem: Qs[d][r], Ks[d][c] (transposed for float4 micro-tile reads),
// Vs[c][d], Ps[r][c]; all rows padded to 68 floats (conflict-free / <=2-way).
// P rows are produced & consumed by the same warp -> __syncwarp only.
// ---------------------------------------------------------------------------
__global__ __launch_bounds__(256) void attn_kernel()
{
    extern __shared__ float sm[];
    float* Qs = sm;                // 64*68
    float* Ks = sm + 64*68;
    float* Vs = sm + 2*64*68;
    float* Ps = sm + 3*64*68;

    const int qt = (gridDim.x - 1) - blockIdx.x;  // heavy (large qt) blocks first
    const int bh = blockIdx.y;
    const int q0 = qt << 6;
    const float* Qg = g_q + (size_t)bh*T_*D_ + (size_t)q0*D_;
    const float* Kg = g_k + (size_t)bh*T_*D_;
    const float* Vg = g_v + (size_t)bh*T_*D_;

    const int tid = threadIdx.x;
    const int tx = tid & 15, ty = tid >> 4;

    // Load Q tile transposed ([d][r]) with 1/sqrt(d) folded in
    {
        const int r  = tid & 63;
        const int dg = tid >> 6;
#pragma unroll
        for (int u = 0; u < 4; u++) {
            int d = (dg*4 + u) << 2;
            float4 v = *(const float4*)(Qg + r*D_ + d);
            Qs[(d+0)*68 + r] = v.x * 0.125f;
            Qs[(d+1)*68 + r] = v.y * 0.125f;
            Qs[(d+2)*68 + r] = v.z * 0.125f;
            Qs[(d+3)*68 + r] = v.w * 0.125f;
        }
    }

    float m_i[4] = {-1e30f, -1e30f, -1e30f, -1e30f};
    float l_i[4] = {0.f, 0.f, 0.f, 0.f};
    float o_acc[4][4];
#pragma unroll
    for (int i = 0; i < 4; i++)
#pragma unroll
        for (int j = 0; j < 4; j++) o_acc[i][j] = 0.f;

    for (int kt = 0; kt <= qt; kt++) {
        const float* Kt = Kg + (size_t)(kt << 6) * D_;
        const float* Vt = Vg + (size_t)(kt << 6) * D_;
        {   // K tile transposed ([d][c])
            const int c  = tid & 63;
            const int dg = tid >> 6;
#pragma unroll
            for (int u = 0; u < 4; u++) {
                int d = (dg*4 + u) << 2;
                float4 v = *(const float4*)(Kt + c*D_ + d);
                Ks[(d+0)*68 + c] = v.x;
                Ks[(d+1)*68 + c] = v.y;
                Ks[(d+2)*68 + c] = v.z;
                Ks[(d+3)*68 + c] = v.w;
            }
        }
        {   // V tile direct ([c][d]), fully coalesced
            const int c  = tid >> 4;
            const int dc = (tid & 15) << 2;
#pragma unroll
            for (int u = 0; u < 4; u++) {
                int cr = c + (u << 4);
                *(float4*)&Vs[cr*68 + dc] = *(const float4*)(Vt + cr*D_ + dc);
            }
        }
        __syncthreads();

        // S = Q K^T  (4x4 micro-tile per thread)
        float s[4][4];
#pragma unroll
        for (int i = 0; i < 4; i++)
#pragma unroll
            for (int j = 0; j < 4; j++) s[i][j] = 0.f;
#pragma unroll 16
        for (int d = 0; d < 64; d++) {
            float a4[4], b4[4];
            *(float4*)a4 = *(const float4*)&Qs[d*68 + (ty<<2)];
            *(float4*)b4 = *(const float4*)&Ks[d*68 + (tx<<2)];
#pragma unroll
            for (int i = 0; i < 4; i++)
#pragma unroll
                for (int j = 0; j < 4; j++) s[i][j] += a4[i]*b4[j];
        }

        if (kt == qt) {   // diagonal tile: causal mask (q0 == k0 here)
#pragma unroll
            for (int i = 0; i < 4; i++)
#pragma unroll
                for (int j = 0; j < 4; j++)
                    if (((tx<<2)+j) > ((ty<<2)+i)) s[i][j] = -1e30f;
        }

        // Online softmax; row groups are 16 contiguous lanes of one warp
#pragma unroll
        for (int i = 0; i < 4; i++) {
            float mx = fmaxf(fmaxf(s[i][0], s[i][1]), fmaxf(s[i][2], s[i][3]));
#pragma unroll
            for (int off = 1; off < 16; off <<= 1)
                mx = fmaxf(mx, __shfl_xor_sync(0xffffffffu, mx, off));
            float mn    = fmaxf(m_i[i], mx);
            float alpha = __expf(m_i[i] - mn);
            m_i[i] = mn;
            float rs = 0.f;
#pragma unroll
            for (int j = 0; j < 4; j++) {
                float p = __expf(s[i][j] - mn);
                s[i][j] = p;
                rs += p;
            }
#pragma unroll
            for (int off = 1; off < 16; off <<= 1)
                rs += __shfl_xor_sync(0xffffffffu, rs, off);
            l_i[i] = l_i[i]*alpha + rs;
#pragma unroll
            for (int j = 0; j < 4; j++) o_acc[i][j] *= alpha;
            *(float4*)&Ps[((ty<<2)+i)*68 + (tx<<2)] =
                make_float4(s[i][0], s[i][1], s[i][2], s[i][3]);
        }
        __syncwarp();   // P rows consumed only within the producing warp

        // O += P @ V
#pragma unroll 4
        for (int c0 = 0; c0 < 64; c0 += 4) {
            float vv[4][4];
#pragma unroll
            for (int u = 0; u < 4; u++)
                *(float4*)vv[u] = *(const float4*)&Vs[(c0+u)*68 + (tx<<2)];
#pragma unroll
            for (int i = 0; i < 4; i++) {
                float pv[4];
                *(float4*)pv = *(const float4*)&Ps[((ty<<2)+i)*68 + c0];
#pragma unroll
                for (int j = 0; j < 4; j++)
                    o_acc[i][j] += pv[0]*vv[0][j] + pv[1]*vv[1][j]
                                 + pv[2]*vv[2][j] + pv[3]*vv[3][j];
            }
        }
        __syncthreads();   // before next K/V tile overwrites smem
    }

    // Epilogue: write [B*T, C] layout (makes proj GEMM reads contiguous)
    const int b = bh >> 4;
    const int h = bh & 15;
    float* dst = g_ao + (size_t)(b*T_ + q0 + (ty<<2))*C_ + (h<<6) + (tx<<2);
#pragma unroll
    for (int i = 0; i < 4; i++) {
        float inv = 1.0f / l_i[i];
        float4 o;
        o.x = o_acc[i][0]*inv; o.y = o_acc[i][1]*inv;
        o.z = o_acc[i][2]*inv; o.w = o_acc[i][3]*inv;
        *(float4*)(dst + (size_t)i*C_) = o;
    }
}

// ---------------------------------------------------------------------------
// Kernel 3: output projection.  out = g_ao @ w_proj + b_proj   [8192,1024]
// ---------------------------------------------------------------------------
__global__ __launch_bounds__(256) void proj_gemm_kernel(
    const float* __restrict__ w, const float* __restrict__ bias,
    float* __restrict__ out)
{
    __shared__ float As[16*68];
    __shared__ float Bs[16*68];

    const int tid = threadIdx.x;
    const int n0 = blockIdx.x * 64;
    const int m0 = blockIdx.y * 64;
    const int tx = tid & 15, ty = tid >> 4;
    const int a_m = tid >> 2,  a_k = (tid & 3) << 2;
    const int b_k = tid >> 4,  b_n = (tid & 15) << 2;

    const float* aptr = g_ao + (size_t)(m0 + a_m) * C_ + a_k;
    const float* bptr = w    + (size_t)b_k * C_ + n0 + b_n;

    float4 av = *(const float4*)aptr;
    float4 bv = *(const float4*)bptr;

    float acc[4][4];
#pragma unroll
    for (int i = 0; i < 4; i++)
#pragma unroll
        for (int j = 0; j < 4; j++) acc[i][j] = 0.f;

    for (int k0 = 0; k0 < C_; k0 += 16) {
        As[(a_k+0)*68 + a_m] = av.x;
        As[(a_k+1)*68 + a_m] = av.y;
        As[(a_k+2)*68 + a_m] = av.z;
        As[(a_k+3)*68 + a_m] = av.w;
        *(float4*)&Bs[b_k*68 + b_n] = bv;
        __syncthreads();
        if (k0 + 16 < C_) {
            av = *(const float4*)(aptr + k0 + 16);
            bv = *(const float4*)(bptr + (size_t)(k0 + 16)*C_);
        }
#pragma unroll
        for (int kk = 0; kk < 16; kk++) {
            float a4[4], b4[4];
            *(float4*)a4 = *(const float4*)&As[kk*68 + (ty<<2)];
            *(float4*)b4 = *(const float4*)&Bs[kk*68 + (tx<<2)];
#pragma unroll
            for (int i = 0; i < 4; i++)
#pragma unroll
                for (int j = 0; j < 4; j++) acc[i][j] += a4[i]*b4[j];
        }
        __syncthreads();
    }

    const int nb = n0 + (tx<<2);
    float bj[4];
#pragma unroll
    for (int j = 0; j < 4; j++) bj[j] = bias[nb + j];
#pragma unroll
    for (int i = 0; i < 4; i++) {
        int m = m0 + (ty<<2) + i;
        float4 o;
        o.x = acc[i][0] + bj[0]; o.y = acc[i][1] + bj[1];
        o.z = acc[i][2] + bj[2]; o.w = acc[i][3] + bj[3];
        *(float4*)(out + (size_t)m*C_ + nb) = o;
    }
}

// ---------------------------------------------------------------------------
extern "C" void kernel_launch(void* const* d_in, const int* in_sizes, int n_in,
                              void* d_out, int out_size)
{
    const float* x      = (const float*)d_in[0];
    const float* w_qkv  = (const float*)d_in[1];
    const float* b_qkv  = (const float*)d_in[2];
    const float* w_proj = (const float*)d_in[3];
    const float* b_proj = (const float*)d_in[4];
    float* out = (float*)d_out;

    const int attn_smem = 4 * 64 * 68 * (int)sizeof(float);  // 69632 B
    cudaFuncSetAttribute(attn_kernel,
                         cudaFuncAttributeMaxDynamicSharedMemorySize, attn_smem);

    dim3 gq(48, 128);   // N=3072/64, M=8192/64
    qkv_gemm_kernel<<<gq, 256>>>(x, w_qkv, b_qkv);

    dim3 ga(32, 64);    // q-tiles, B*H
    attn_kernel<<<ga, 256, attn_smem>>>();

    dim3 gp(16, 128);   // N=1024/64, M=8192/64
    proj_gemm_kernel<<<gp, 256>>>(w_proj, b_proj, out);
}

// round 2
// speedup vs baseline: 2.9069x; 2.9069x over previous
#include <cuda_runtime.h>

#define B_ 4
#define T_ 2048
#define C_ 1024
#define H_ 16
#define D_ 64
#define M_ (B_*T_)

// Scratch (device globals; allocation-free per harness rules)
__device__ float g_q [B_*H_*T_*D_];   // [B,H,T,d]
__device__ float g_k [B_*H_*T_*D_];
__device__ float g_v [B_*H_*T_*D_];
__device__ float g_ao[M_*C_];         // attention output, [B*T, C]

// ---------------------------------------------------------------------------
// helpers
// ---------------------------------------------------------------------------
__device__ __forceinline__ unsigned f2tf(float x) {
    unsigned r;
    asm("cvt.rna.tf32.f32 %0, %1;" : "=r"(r) : "f"(x));
    return r;
}
__device__ __forceinline__ float f2tf_f(float x) {
    return __uint_as_float(f2tf(x));
}
// D = A(16x8,row) * B(8x8,col) + C, tf32 inputs, f32 accum
__device__ __forceinline__ void mma_tf32(float* d, const unsigned* a,
                                         const unsigned* b, const float* c) {
    asm volatile(
        "mma.sync.aligned.m16n8k8.row.col.f32.tf32.tf32.f32 "
        "{%0,%1,%2,%3}, {%4,%5,%6,%7}, {%8,%9}, {%10,%11,%12,%13};\n"
        : "=f"(d[0]), "=f"(d[1]), "=f"(d[2]), "=f"(d[3])
        : "r"(a[0]), "r"(a[1]), "r"(a[2]), "r"(a[3]),
          "r"(b[0]), "r"(b[1]),
          "f"(c[0]), "f"(c[1]), "f"(c[2]), "f"(c[3]));
}

// ---------------------------------------------------------------------------
// GEMM: out[m,n] = A[m,:] @ W[:,n] + bias[n].  Block tile 128x128, K-step 32.
// 8 warps = 4(M) x 2(N); warp tile 32x64 = 2 m16 x 8 n8 fragments.
// SCATTER=true: epilogue scatters qkv into g_q/g_k/g_v ([B,H,T,d]).
// ---------------------------------------------------------------------------
template<int LDN, bool SCATTER>
__global__ __launch_bounds__(256) void mma_gemm(
    const float* __restrict__ A, const float* __restrict__ Wm,
    const float* __restrict__ bias, float* __restrict__ out)
{
    __shared__ float As[128*36];     // [m][k] pad 36 -> frag loads conflict-free
    __shared__ float Bs[32*136];     // [k][n] pad 136 -> frag loads conflict-free

    const int tid  = threadIdx.x;
    const int lane = tid & 31, w = tid >> 5;
    const int g = lane >> 2, ctg = lane & 3;
    const int wm = (w >> 1) << 5;    // 0,32,64,96
    const int wn = (w & 1)  << 6;    // 0,64
    const int m0 = blockIdx.y << 7, n0 = blockIdx.x << 7;

    float acc[2][8][4];
#pragma unroll
    for (int mt = 0; mt < 2; mt++)
#pragma unroll
        for (int nf = 0; nf < 8; nf++)
#pragma unroll
            for (int r = 0; r < 4; r++) acc[mt][nf][r] = 0.f;

    float4 areg[4], breg[4];
#pragma unroll
    for (int i = 0; i < 4; i++) {
        int fid = i*256 + tid;
        int r = fid >> 3, c = (fid & 7) << 2;          // A: 8 f4 per 32-wide row
        areg[i] = *(const float4*)(A + (size_t)(m0 + r)*C_ + c);
        int rb = fid >> 5, cb = (fid & 31) << 2;       // B: 32 f4 per 128-wide row
        breg[i] = *(const float4*)(Wm + (size_t)rb*LDN + n0 + cb);
    }

    for (int k0 = 0; k0 < C_; k0 += 32) {
#pragma unroll
        for (int i = 0; i < 4; i++) {
            int fid = i*256 + tid;
            int r = fid >> 3, c = (fid & 7) << 2;
            float4 a = areg[i];
            *(float4*)&As[r*36 + c] = make_float4(f2tf_f(a.x), f2tf_f(a.y),
                                                  f2tf_f(a.z), f2tf_f(a.w));
            int rb = fid >> 5, cb = (fid & 31) << 2;
            float4 b = breg[i];
            *(float4*)&Bs[rb*136 + cb] = make_float4(f2tf_f(b.x), f2tf_f(b.y),
                                                     f2tf_f(b.z), f2tf_f(b.w));
        }
        __syncthreads();
        if (k0 + 32 < C_) {
#pragma unroll
            for (int i = 0; i < 4; i++) {
                int fid = i*256 + tid;
                int r = fid >> 3, c = (fid & 7) << 2;
                areg[i] = *(const float4*)(A + (size_t)(m0 + r)*C_ + k0 + 32 + c);
                int rb = fid >> 5, cb = (fid & 31) << 2;
                breg[i] = *(const float4*)(Wm + (size_t)(k0 + 32 + rb)*LDN + n0 + cb);
            }
        }
#pragma unroll
        for (int kk = 0; kk < 4; kk++) {
            unsigned afr[2][4];
#pragma unroll
            for (int mt = 0; mt < 2; mt++) {
                int rb = wm + (mt << 4);
                afr[mt][0] = __float_as_uint(As[(rb+g  )*36 + (kk<<3) + ctg    ]);
                afr[mt][1] = __float_as_uint(As[(rb+g+8)*36 + (kk<<3) + ctg    ]);
                afr[mt][2] = __float_as_uint(As[(rb+g  )*36 + (kk<<3) + ctg + 4]);
                afr[mt][3] = __float_as_uint(As[(rb+g+8)*36 + (kk<<3) + ctg + 4]);
            }
#pragma unroll
            for (int nf = 0; nf < 8; nf++) {
                unsigned bfr[2];
                bfr[0] = __float_as_uint(Bs[((kk<<3)+ctg  )*136 + wn + (nf<<3) + g]);
                bfr[1] = __float_as_uint(Bs[((kk<<3)+ctg+4)*136 + wn + (nf<<3) + g]);
                mma_tf32(acc[0][nf], afr[0], bfr, acc[0][nf]);
                mma_tf32(acc[1][nf], afr[1], bfr, acc[1][nf]);
            }
        }
        __syncthreads();
    }

    // Epilogue
#pragma unroll
    for (int mt = 0; mt < 2; mt++) {
#pragma unroll
        for (int nf = 0; nf < 8; nf++) {
            int col = n0 + wn + (nf << 3) + (ctg << 1);
            int r0  = m0 + wm + (mt << 4) + g;
            float b0 = bias[col], b1 = bias[col + 1];
            float2 v0 = make_float2(acc[mt][nf][0] + b0, acc[mt][nf][1] + b1);
            float2 v1 = make_float2(acc[mt][nf][2] + b0, acc[mt][nf][3] + b1);
            if (SCATTER) {
                int sect = col >> 10, cc = col & 1023;
                int h = cc >> 6, dd = cc & 63;
                float* dst = (sect == 0) ? g_q : (sect == 1) ? g_k : g_v;
                int bb0 = r0 >> 11, t0 = r0 & (T_-1);
                int r1 = r0 + 8, bb1 = r1 >> 11, t1 = r1 & (T_-1);
                *(float2*)(dst + (((size_t)bb0*H_ + h)*T_ + t0)*D_ + dd) = v0;
                *(float2*)(dst + (((size_t)bb1*H_ + h)*T_ + t1)*D_ + dd) = v1;
            } else {
                *(float2*)(out + (size_t)r0*LDN + col) = v0;
                *(float2*)(out + (size_t)(r0+8)*LDN + col) = v1;
            }
        }
    }
}

// ---------------------------------------------------------------------------
// Causal flash attention with tensor cores.
// Block = (bh, 128 q-rows); 8 warps, each owns a 16-row q stripe.
// Q lives in registers as A-fragments for the whole kernel.
// Per 64-col K/V tile: S = QK^T (tensor), online softmax (shfl, no smem),
// P -> smem (per-warp region, __syncwarp only), O += P@V (tensor).
// ---------------------------------------------------------------------------
__global__ __launch_bounds__(256) void attn_mma()
{
    extern __shared__ float sm[];
    float* Ks = sm;                  // [kcol 64][d 64] pad 68
    float* Vs = sm + 64*68;          // [k 64][d 64]    pad 72 (conflict-free B-frags)
    float* Ps = sm + 64*68 + 64*72;  // per warp [16][64] pad 68

    const int tid  = threadIdx.x;
    const int lane = tid & 31, w = tid >> 5;
    const int g = lane >> 2, ctg = lane & 3;
    const int qb = (gridDim.x - 1) - blockIdx.x;   // heavy blocks first
    const int bh = blockIdx.y;
    const int q0 = qb << 7;
    const int wq = q0 + (w << 4);                  // this warp's first q row
    float* Pw = Ps + w * 16 * 68;

    const float* Qg = g_q + (size_t)bh * T_ * D_;
    const float* Kg = g_k + (size_t)bh * T_ * D_;
    const float* Vg = g_v + (size_t)bh * T_ * D_;

    // Q A-fragments (scale 1/sqrt(64) folded in): 8 k8-chunks over d=64
    unsigned aq[8][4];
#pragma unroll
    for (int j = 0; j < 8; j++) {
        aq[j][0] = f2tf(Qg[(wq+g  )*D_ + (j<<3) + ctg    ] * 0.125f);
        aq[j][1] = f2tf(Qg[(wq+g+8)*D_ + (j<<3) + ctg    ] * 0.125f);
        aq[j][2] = f2tf(Qg[(wq+g  )*D_ + (j<<3) + ctg + 4] * 0.125f);
        aq[j][3] = f2tf(Qg[(wq+g+8)*D_ + (j<<3) + ctg + 4] * 0.125f);
    }

    float m_i[2] = {-1e30f, -1e30f};
    float l_i[2] = {0.f, 0.f};
    float o[8][4];
#pragma unroll
    for (int nf = 0; nf < 8; nf++)
#pragma unroll
        for (int r = 0; r < 4; r++) o[nf][r] = 0.f;

    const int nkt = (q0 >> 6) + 2;
    for (int kt = 0; kt < nkt; kt++) {
        const float* Kt = Kg + (size_t)(kt << 6) * D_;
        const float* Vt = Vg + (size_t)(kt << 6) * D_;
#pragma unroll
        for (int i = 0; i < 4; i++) {
            int fid = i*256 + tid;
            int r = fid >> 4, c = (fid & 15) << 2;
            float4 kv = *(const float4*)(Kt + r*D_ + c);
            *(float4*)&Ks[r*68 + c] = make_float4(f2tf_f(kv.x), f2tf_f(kv.y),
                                                  f2tf_f(kv.z), f2tf_f(kv.w));
            float4 vv = *(const float4*)(Vt + r*D_ + c);
            *(float4*)&Vs[r*72 + c] = make_float4(f2tf_f(vv.x), f2tf_f(vv.y),
                                                  f2tf_f(vv.z), f2tf_f(vv.w));
        }
        __syncthreads();

        // S = Q K^T : A = Q chunk kk, B[k=d][n=kcol] = Ks[kcol][d]
        float s[8][4];
#pragma unroll
        for (int nf = 0; nf < 8; nf++)
#pragma unroll
            for (int r = 0; r < 4; r++) s[nf][r] = 0.f;
#pragma unroll
        for (int kk = 0; kk < 8; kk++) {
#pragma unroll
            for (int nf = 0; nf < 8; nf++) {
                unsigned bk[2];
                bk[0] = __float_as_uint(Ks[((nf<<3)+g)*68 + (kk<<3) + ctg    ]);
                bk[1] = __float_as_uint(Ks[((nf<<3)+g)*68 + (kk<<3) + ctg + 4]);
                mma_tf32(s[nf], aq[kk], bk, s[nf]);
            }
        }

        // causal mask (only possible on the last tiles of this warp's stripe)
        if ((kt << 6) + 63 > wq) {
#pragma unroll
            for (int nf = 0; nf < 8; nf++) {
                int col = (kt << 6) + (nf << 3) + (ctg << 1);
                int r0 = wq + g, r1 = wq + g + 8;
                if (col     > r0) s[nf][0] = -1e30f;
                if (col + 1 > r0) s[nf][1] = -1e30f;
                if (col     > r1) s[nf][2] = -1e30f;
                if (col + 1 > r1) s[nf][3] = -1e30f;
            }
        }

        // online softmax, rows r0 (regs 0,1) and r1 (regs 2,3);
        // a row lives on lanes 4g..4g+3 -> shfl_xor 1,2
        float alpha[2];
#pragma unroll
        for (int rr = 0; rr < 2; rr++) {
            float mx = -1e30f;
#pragma unroll
            for (int nf = 0; nf < 8; nf++)
                mx = fmaxf(mx, fmaxf(s[nf][rr*2], s[nf][rr*2+1]));
            mx = fmaxf(mx, __shfl_xor_sync(0xffffffffu, mx, 1));
            mx = fmaxf(mx, __shfl_xor_sync(0xffffffffu, mx, 2));
            float mn = fmaxf(m_i[rr], mx);
            alpha[rr] = __expf(m_i[rr] - mn);
            m_i[rr] = mn;
            float rs = 0.f;
#pragma unroll
            for (int nf = 0; nf < 8; nf++) {
                float p0 = __expf(s[nf][rr*2]   - mn);
                float p1 = __expf(s[nf][rr*2+1] - mn);
                s[nf][rr*2] = p0; s[nf][rr*2+1] = p1;
                rs += p0 + p1;
            }
            rs += __shfl_xor_sync(0xffffffffu, rs, 1);
            rs += __shfl_xor_sync(0xffffffffu, rs, 2);
            l_i[rr] = l_i[rr]*alpha[rr] + rs;
#pragma unroll
            for (int nf = 0; nf < 8; nf++) {
                o[nf][rr*2]   *= alpha[rr];
                o[nf][rr*2+1] *= alpha[rr];
            }
        }

        // P -> per-warp smem (tf32), rows g and g+8
#pragma unroll
        for (int nf = 0; nf < 8; nf++) {
            *(float2*)&Pw[ g    *68 + (nf<<3) + (ctg<<1)] =
                make_float2(f2tf_f(s[nf][0]), f2tf_f(s[nf][1]));
            *(float2*)&Pw[(g+8) *68 + (nf<<3) + (ctg<<1)] =
                make_float2(f2tf_f(s[nf][2]), f2tf_f(s[nf][3]));
        }
        __syncwarp();

        // O += P @ V : A = P (16x64), B[k][n=d] = Vs[k][d]
#pragma unroll
        for (int kk = 0; kk < 8; kk++) {
            unsigned ap[4];
            ap[0] = __float_as_uint(Pw[ g    *68 + (kk<<3) + ctg    ]);
            ap[1] = __float_as_uint(Pw[(g+8) *68 + (kk<<3) + ctg    ]);
            ap[2] = __float_as_uint(Pw[ g    *68 + (kk<<3) + ctg + 4]);
            ap[3] = __float_as_uint(Pw[(g+8) *68 + (kk<<3) + ctg + 4]);
#pragma unroll
            for (int nf = 0; nf < 8; nf++) {
                unsigned bv[2];
                bv[0] = __float_as_uint(Vs[((kk<<3)+ctg  )*72 + (nf<<3) + g]);
                bv[1] = __float_as_uint(Vs[((kk<<3)+ctg+4)*72 + (nf<<3) + g]);
                mma_tf32(o[nf], ap, bv, o[nf]);
            }
        }
        __syncthreads();
    }

    // epilogue: write [B*T, C]
    const int b = bh >> 4, h = bh & 15;
    float inv0 = 1.0f / l_i[0], inv1 = 1.0f / l_i[1];
#pragma unroll
    for (int nf = 0; nf < 8; nf++) {
        int dd = (nf << 3) + (ctg << 1);
        size_t base0 = (size_t)(b*T_ + wq + g    )*C_ + (h << 6) + dd;
        size_t base1 = (size_t)(b*T_ + wq + g + 8)*C_ + (h << 6) + dd;
        *(float2*)(g_ao + base0) = make_float2(o[nf][0]*inv0, o[nf][1]*inv0);
        *(float2*)(g_ao + base1) = make_float2(o[nf][2]*inv1, o[nf][3]*inv1);
    }
}

// ---------------------------------------------------------------------------
extern "C" void kernel_launch(void* const* d_in, const int* in_sizes, int n_in,
                              void* d_out, int out_size)
{
    const float* x      = (const float*)d_in[0];
    const float* w_qkv  = (const float*)d_in[1];
    const float* b_qkv  = (const float*)d_in[2];
    const float* w_proj = (const float*)d_in[3];
    const float* b_proj = (const float*)d_in[4];
    float* out = (float*)d_out;

    float* ao_ptr = nullptr;
    cudaGetSymbolAddress((void**)&ao_ptr, g_ao);

    const int attn_smem = (64*68 + 64*72 + 8*16*68) * (int)sizeof(float); // 70656
    cudaFuncSetAttribute(attn_mma,
                         cudaFuncAttributeMaxDynamicSharedMemorySize, attn_smem);

    dim3 gq(24, 64);   // N=3072/128, M=8192/128
    mma_gemm<3*C_, true><<<gq, 256>>>(x, w_qkv, b_qkv, nullptr);

    dim3 ga(16, 64);   // q-blocks (128 rows), B*H
    attn_mma<<<ga, 256, attn_smem>>>();

    dim3 gp(8, 64);    // N=1024/128, M=8192/128
    mma_gemm<C_, false><<<gp, 256>>>(ao_ptr, w_proj, b_proj, out);
}

// round 3
// speedup vs baseline: 3.4772x; 1.1962x over previous
#include <cuda_runtime.h>

#define B_ 4
#define T_ 2048
#define C_ 1024
#define H_ 16
#define D_ 64
#define M_ (B_*T_)

// Scratch (device globals; allocation-free per harness rules)
__device__ float g_q [B_*H_*T_*D_];   // [B,H,T,d]
__device__ float g_k [B_*H_*T_*D_];
__device__ float g_v [B_*H_*T_*D_];
__device__ float g_ao[M_*C_];         // attention output, [B*T, C]

// ---------------------------------------------------------------------------
// helpers
// ---------------------------------------------------------------------------
__device__ __forceinline__ unsigned f2tf(float x) {
    unsigned r;
    asm("cvt.rna.tf32.f32 %0, %1;" : "=r"(r) : "f"(x));
    return r;
}
__device__ __forceinline__ float f2tf_f(float x) {
    return __uint_as_float(f2tf(x));
}
// D = A(16x8,row) * B(8x8,col) + C, tf32 inputs, f32 accum
__device__ __forceinline__ void mma_tf32(float* d, const unsigned* a,
                                         const unsigned* b, const float* c) {
    asm volatile(
        "mma.sync.aligned.m16n8k8.row.col.f32.tf32.tf32.f32 "
        "{%0,%1,%2,%3}, {%4,%5,%6,%7}, {%8,%9}, {%10,%11,%12,%13};\n"
        : "=f"(d[0]), "=f"(d[1]), "=f"(d[2]), "=f"(d[3])
        : "r"(a[0]), "r"(a[1]), "r"(a[2]), "r"(a[3]),
          "r"(b[0]), "r"(b[1]),
          "f"(c[0]), "f"(c[1]), "f"(c[2]), "f"(c[3]));
}

#define AS_ST (128*36)
#define BS_ST (32*136)

// ---------------------------------------------------------------------------
// GEMM: out[m,n] = A[m,:] @ W[:,n] + bias[n].  Block tile 128x128, K-step 32,
// two smem stages (ping/pong), ONE barrier per K-step.
// 8 warps = 4(M) x 2(N); warp tile 32x64 = 2 m16 x 8 n8 fragments.
// SCATTER=true: epilogue scatters qkv into g_q/g_k/g_v ([B,H,T,d]).
// ---------------------------------------------------------------------------
template<int LDN, bool SCATTER>
__global__ __launch_bounds__(256) void mma_gemm(
    const float* __restrict__ A, const float* __restrict__ Wm,
    const float* __restrict__ bias, float* __restrict__ out)
{
    extern __shared__ float smg[];
    float* AsBase = smg;                 // [2][128*36]  ([m][k], pad 36)
    float* BsBase = smg + 2*AS_ST;       // [2][32*136]  ([k][n], pad 136)

    const int tid  = threadIdx.x;
    const int lane = tid & 31, w = tid >> 5;
    const int g = lane >> 2, ctg = lane & 3;
    const int wm = (w >> 1) << 5;    // 0,32,64,96
    const int wn = (w & 1)  << 6;    // 0,64
    const int m0 = blockIdx.y << 7, n0 = blockIdx.x << 7;

    const int a_r = tid >> 3,  a_c = (tid & 7) << 2;    // A: 8 f4 per 32-wide row
    const int b_r = tid >> 5,  b_c = (tid & 31) << 2;   // B: 32 f4 per 128-wide row

    float acc[2][8][4];
#pragma unroll
    for (int mt = 0; mt < 2; mt++)
#pragma unroll
        for (int nf = 0; nf < 8; nf++)
#pragma unroll
            for (int r = 0; r < 4; r++) acc[mt][nf][r] = 0.f;

    float4 areg[4], breg[4];
#pragma unroll
    for (int i = 0; i < 4; i++) {
        areg[i] = *(const float4*)(A + (size_t)(m0 + i*32 + a_r)*C_ + a_c);
        breg[i] = *(const float4*)(Wm + (size_t)(i*8 + b_r)*LDN + n0 + b_c);
    }

    int buf = 0;
#pragma unroll 1
    for (int k0 = 0; k0 < C_; k0 += 32) {
        float* Asb = AsBase + buf*AS_ST;
        float* Bsb = BsBase + buf*BS_ST;
        // stage prefetched tile into smem[buf]
#pragma unroll
        for (int i = 0; i < 4; i++) {
            float4 a = areg[i];
            *(float4*)&Asb[(i*32 + a_r)*36 + a_c] =
                make_float4(f2tf_f(a.x), f2tf_f(a.y), f2tf_f(a.z), f2tf_f(a.w));
            float4 b = breg[i];
            *(float4*)&Bsb[(i*8 + b_r)*136 + b_c] =
                make_float4(f2tf_f(b.x), f2tf_f(b.y), f2tf_f(b.z), f2tf_f(b.w));
        }
        __syncthreads();
        // prefetch next gmem tile (drains under the MMA block below)
        if (k0 + 32 < C_) {
#pragma unroll
            for (int i = 0; i < 4; i++) {
                areg[i] = *(const float4*)(A + (size_t)(m0 + i*32 + a_r)*C_ + k0 + 32 + a_c);
                breg[i] = *(const float4*)(Wm + (size_t)(k0 + 32 + i*8 + b_r)*LDN + n0 + b_c);
            }
        }
        // compute from smem[buf]
#pragma unroll
        for (int kk = 0; kk < 4; kk++) {
            unsigned afr[2][4];
#pragma unroll
            for (int mt = 0; mt < 2; mt++) {
                int rb = wm + (mt << 4);
                afr[mt][0] = __float_as_uint(Asb[(rb+g  )*36 + (kk<<3) + ctg    ]);
                afr[mt][1] = __float_as_uint(Asb[(rb+g+8)*36 + (kk<<3) + ctg    ]);
                afr[mt][2] = __float_as_uint(Asb[(rb+g  )*36 + (kk<<3) + ctg + 4]);
                afr[mt][3] = __float_as_uint(Asb[(rb+g+8)*36 + (kk<<3) + ctg + 4]);
            }
#pragma unroll
            for (int nf = 0; nf < 8; nf++) {
                unsigned bfr[2];
                bfr[0] = __float_as_uint(Bsb[((kk<<3)+ctg  )*136 + wn + (nf<<3) + g]);
                bfr[1] = __float_as_uint(Bsb[((kk<<3)+ctg+4)*136 + wn + (nf<<3) + g]);
                mma_tf32(acc[0][nf], afr[0], bfr, acc[0][nf]);
                mma_tf32(acc[1][nf], afr[1], bfr, acc[1][nf]);
            }
        }
        buf ^= 1;
    }

    // Epilogue
#pragma unroll
    for (int mt = 0; mt < 2; mt++) {
#pragma unroll
        for (int nf = 0; nf < 8; nf++) {
            int col = n0 + wn + (nf << 3) + (ctg << 1);
            int r0  = m0 + wm + (mt << 4) + g;
            float b0 = bias[col], b1 = bias[col + 1];
            float2 v0 = make_float2(acc[mt][nf][0] + b0, acc[mt][nf][1] + b1);
            float2 v1 = make_float2(acc[mt][nf][2] + b0, acc[mt][nf][3] + b1);
            if (SCATTER) {
                int sect = col >> 10, cc = col & 1023;
                int h = cc >> 6, dd = cc & 63;
                float* dst = (sect == 0) ? g_q : (sect == 1) ? g_k : g_v;
                int bb0 = r0 >> 11, t0 = r0 & (T_-1);
                int r1 = r0 + 8, bb1 = r1 >> 11, t1 = r1 & (T_-1);
                *(float2*)(dst + (((size_t)bb0*H_ + h)*T_ + t0)*D_ + dd) = v0;
                *(float2*)(dst + (((size_t)bb1*H_ + h)*T_ + t1)*D_ + dd) = v1;
            } else {
                *(float2*)(out + (size_t)r0*LDN + col) = v0;
                *(float2*)(out + (size_t)(r0+8)*LDN + col) = v1;
            }
        }
    }
}

#define KS_ST (64*68)
#define VS_ST (64*72)

// ---------------------------------------------------------------------------
// Causal flash attention with tensor cores, two-stage K/V smem pipeline.
// Block = (bh, 128 q-rows); 8 warps, each owns a 16-row q stripe.
// Q lives in registers as A-fragments for the whole kernel (log2e folded in).
// Per 64-col K/V tile: S = QK^T (tensor), online softmax (shfl, exp2),
// P -> smem (per-warp region, __syncwarp only), O += P@V (tensor).
// ONE __syncthreads per tile.
// ---------------------------------------------------------------------------
__global__ __launch_bounds__(256) void attn_mma()
{
    extern __shared__ float sm[];
    float* KsBase = sm;                        // [2][64][68]
    float* VsBase = sm + 2*KS_ST;              // [2][64][72]
    float* Ps     = sm + 2*KS_ST + 2*VS_ST;    // per warp [16][68]

    const int tid  = threadIdx.x;
    const int lane = tid & 31, w = tid >> 5;
    const int g = lane >> 2, ctg = lane & 3;
    const int qb = (gridDim.x - 1) - blockIdx.x;   // heavy blocks first
    const int bh = blockIdx.y;
    const int q0 = qb << 7;
    const int wq = q0 + (w << 4);                  // this warp's first q row
    float* Pw = Ps + w * 16 * 68;

    const float* Qg = g_q + (size_t)bh * T_ * D_;
    const float* Kg = g_k + (size_t)bh * T_ * D_;
    const float* Vg = g_v + (size_t)bh * T_ * D_;

    // Q A-fragments; scale = 1/sqrt(64) * log2(e)  (softmax done in exp2 domain)
    const float qsc = 0.125f * 1.4426950408889634f;
    unsigned aq[8][4];
#pragma unroll
    for (int j = 0; j < 8; j++) {
        aq[j][0] = f2tf(Qg[(wq+g  )*D_ + (j<<3) + ctg    ] * qsc);
        aq[j][1] = f2tf(Qg[(wq+g+8)*D_ + (j<<3) + ctg    ] * qsc);
        aq[j][2] = f2tf(Qg[(wq+g  )*D_ + (j<<3) + ctg + 4] * qsc);
        aq[j][3] = f2tf(Qg[(wq+g+8)*D_ + (j<<3) + ctg + 4] * qsc);
    }

    float m_i[2] = {-1e30f, -1e30f};
    float l_i[2] = {0.f, 0.f};
    float o[8][4];
#pragma unroll
    for (int nf = 0; nf < 8; nf++)
#pragma unroll
        for (int r = 0; r < 4; r++) o[nf][r] = 0.f;

    const int ld_r = tid >> 4, ld_c = (tid & 15) << 2;   // 16 rows/iter, 4 iters

    // prefetch tile 0 into regs
    float4 kreg[4], vreg[4];
#pragma unroll
    for (int i = 0; i < 4; i++) {
        kreg[i] = *(const float4*)(Kg + (size_t)(i*16 + ld_r)*D_ + ld_c);
        vreg[i] = *(const float4*)(Vg + (size_t)(i*16 + ld_r)*D_ + ld_c);
    }

    int buf = 0;
    const int nkt = (q0 >> 6) + 2;
#pragma unroll 1
    for (int kt = 0; kt < nkt; kt++) {
        float* Ksb = KsBase + buf*KS_ST;
        float* Vsb = VsBase + buf*VS_ST;
        // stage prefetched tile into smem[buf] (tf32-rounded)
#pragma unroll
        for (int i = 0; i < 4; i++) {
            float4 kv = kreg[i];
            *(float4*)&Ksb[(i*16 + ld_r)*68 + ld_c] =
                make_float4(f2tf_f(kv.x), f2tf_f(kv.y), f2tf_f(kv.z), f2tf_f(kv.w));
            float4 vv = vreg[i];
            *(float4*)&Vsb[(i*16 + ld_r)*72 + ld_c] =
                make_float4(f2tf_f(vv.x), f2tf_f(vv.y), f2tf_f(vv.z), f2tf_f(vv.w));
        }
        __syncthreads();
        // prefetch next tile
        if (kt + 1 < nkt) {
            const float* Kt = Kg + (size_t)((kt+1) << 6) * D_;
            const float* Vt = Vg + (size_t)((kt+1) << 6) * D_;
#pragma unroll
            for (int i = 0; i < 4; i++) {
                kreg[i] = *(const float4*)(Kt + (size_t)(i*16 + ld_r)*D_ + ld_c);
                vreg[i] = *(const float4*)(Vt + (size_t)(i*16 + ld_r)*D_ + ld_c);
            }
        }

        // S = Q K^T : A = Q chunk kk, B[k=d][n=kcol] = Ksb[kcol][d]
        float s[8][4];
#pragma unroll
        for (int nf = 0; nf < 8; nf++)
#pragma unroll
            for (int r = 0; r < 4; r++) s[nf][r] = 0.f;
#pragma unroll
        for (int kk = 0; kk < 8; kk++) {
#pragma unroll
            for (int nf = 0; nf < 8; nf++) {
                unsigned bk[2];
                bk[0] = __float_as_uint(Ksb[((nf<<3)+g)*68 + (kk<<3) + ctg    ]);
                bk[1] = __float_as_uint(Ksb[((nf<<3)+g)*68 + (kk<<3) + ctg + 4]);
                mma_tf32(s[nf], aq[kk], bk, s[nf]);
            }
        }

        // causal mask (only tiles overlapping this warp's diagonal)
        if ((kt << 6) + 63 > wq) {
#pragma unroll
            for (int nf = 0; nf < 8; nf++) {
                int col = (kt << 6) + (nf << 3) + (ctg << 1);
                int r0 = wq + g, r1 = wq + g + 8;
                if (col     > r0) s[nf][0] = -1e30f;
                if (col + 1 > r0) s[nf][1] = -1e30f;
                if (col     > r1) s[nf][2] = -1e30f;
                if (col + 1 > r1) s[nf][3] = -1e30f;
            }
        }

        // online softmax (exp2 domain); a row lives on lanes 4g..4g+3
        float alpha[2];
#pragma unroll
        for (int rr = 0; rr < 2; rr++) {
            float mx = -1e30f;
#pragma unroll
            for (int nf = 0; nf < 8; nf++)
                mx = fmaxf(mx, fmaxf(s[nf][rr*2], s[nf][rr*2+1]));
            mx = fmaxf(mx, __shfl_xor_sync(0xffffffffu, mx, 1));
            mx = fmaxf(mx, __shfl_xor_sync(0xffffffffu, mx, 2));
            float mn = fmaxf(m_i[rr], mx);
            alpha[rr] = exp2f(m_i[rr] - mn);
            m_i[rr] = mn;
            float rs = 0.f;
#pragma unroll
            for (int nf = 0; nf < 8; nf++) {
                float p0 = exp2f(s[nf][rr*2]   - mn);
                float p1 = exp2f(s[nf][rr*2+1] - mn);
                s[nf][rr*2] = p0; s[nf][rr*2+1] = p1;
                rs += p0 + p1;
            }
            rs += __shfl_xor_sync(0xffffffffu, rs, 1);
            rs += __shfl_xor_sync(0xffffffffu, rs, 2);
            l_i[rr] = l_i[rr]*alpha[rr] + rs;
#pragma unroll
            for (int nf = 0; nf < 8; nf++) {
                o[nf][rr*2]   *= alpha[rr];
                o[nf][rr*2+1] *= alpha[rr];
            }
        }

        // P -> per-warp smem (tf32), rows g and g+8
#pragma unroll
        for (int nf = 0; nf < 8; nf++) {
            *(float2*)&Pw[ g    *68 + (nf<<3) + (ctg<<1)] =
                make_float2(f2tf_f(s[nf][0]), f2tf_f(s[nf][1]));
            *(float2*)&Pw[(g+8) *68 + (nf<<3) + (ctg<<1)] =
                make_float2(f2tf_f(s[nf][2]), f2tf_f(s[nf][3]));
        }
        __syncwarp();

        // O += P @ V : A = P (16x64), B[k][n=d] = Vsb[k][d]
#pragma unroll
        for (int kk = 0; kk < 8; kk++) {
            unsigned ap[4];
            ap[0] = __float_as_uint(Pw[ g    *68 + (kk<<3) + ctg    ]);
            ap[1] = __float_as_uint(Pw[(g+8) *68 + (kk<<3) + ctg    ]);
            ap[2] = __float_as_uint(Pw[ g    *68 + (kk<<3) + ctg + 4]);
            ap[3] = __float_as_uint(Pw[(g+8) *68 + (kk<<3) + ctg + 4]);
#pragma unroll
            for (int nf = 0; nf < 8; nf++) {
                unsigned bv[2];
                bv[0] = __float_as_uint(Vsb[((kk<<3)+ctg  )*72 + (nf<<3) + g]);
                bv[1] = __float_as_uint(Vsb[((kk<<3)+ctg+4)*72 + (nf<<3) + g]);
                mma_tf32(o[nf], ap, bv, o[nf]);
            }
        }
        buf ^= 1;
    }

    // epilogue: write [B*T, C]
    const int b = bh >> 4, h = bh & 15;
    float inv0 = 1.0f / l_i[0], inv1 = 1.0f / l_i[1];
#pragma unroll
    for (int nf = 0; nf < 8; nf++) {
        int dd = (nf << 3) + (ctg << 1);
        size_t base0 = (size_t)(b*T_ + wq + g    )*C_ + (h << 6) + dd;
        size_t base1 = (size_t)(b*T_ + wq + g + 8)*C_ + (h << 6) + dd;
        *(float2*)(g_ao + base0) = make_float2(o[nf][0]*inv0, o[nf][1]*inv0);
        *(float2*)(g_ao + base1) = make_float2(o[nf][2]*inv1, o[nf][3]*inv1);
    }
}

// ---------------------------------------------------------------------------
extern "C" void kernel_launch(void* const* d_in, const int* in_sizes, int n_in,
                              void* d_out, int out_size)
{
    const float* x      = (const float*)d_in[0];
    const float* w_qkv  = (const float*)d_in[1];
    const float* b_qkv  = (const float*)d_in[2];
    const float* w_proj = (const float*)d_in[3];
    const float* b_proj = (const float*)d_in[4];
    float* out = (float*)d_out;

    float* ao_ptr = nullptr;
    cudaGetSymbolAddress((void**)&ao_ptr, g_ao);

    const int gemm_smem = (2*AS_ST + 2*BS_ST) * (int)sizeof(float);          // 71680
    const int attn_smem = (2*KS_ST + 2*VS_ST + 8*16*68) * (int)sizeof(float); // 106496

    cudaFuncSetAttribute(mma_gemm<3*C_, true>,
                         cudaFuncAttributeMaxDynamicSharedMemorySize, gemm_smem);
    cudaFuncSetAttribute(mma_gemm<C_, false>,
                         cudaFuncAttributeMaxDynamicSharedMemorySize, gemm_smem);
    cudaFuncSetAttribute(attn_mma,
                         cudaFuncAttributeMaxDynamicSharedMemorySize, attn_smem);

    dim3 gq(24, 64);   // N=3072/128, M=8192/128
    mma_gemm<3*C_, true><<<gq, 256, gemm_smem>>>(x, w_qkv, b_qkv, nullptr);

    dim3 ga(16, 64);   // q-blocks (128 rows), B*H
    attn_mma<<<ga, 256, attn_smem>>>();

    dim3 gp(8, 64);    // N=1024/128, M=8192/128
    mma_gemm<C_, false><<<gp, 256, gemm_smem>>>(ao_ptr, w_proj, b_proj, out);
}